// round 1
// baseline (speedup 1.0000x reference)
#include <cuda_runtime.h>
#include <math.h>

#define BB 4
#define LL 2048
#define DD 1024
#define HH 16
#define DHH 64
#define M_ROWS (BB * LL)   // 8192

// Scratch (allocation-free): q,k,v in [B*H, L, DH]; ctx in [B, L, D]
__device__ float g_q[BB * HH * LL * DHH];
__device__ float g_k[BB * HH * LL * DHH];
__device__ float g_v[BB * HH * LL * DHH];
__device__ float g_ctx[BB * LL * DD];

// ---------------------------------------------------------------------------
// Kernel 1: QKV GEMM  y[m,n] = sum_k x[m,k] * w_qkv[n,k]
// M=8192, N=3072, K=1024. Tile 64x64x32, 256 threads, 4x4 per thread.
// Epilogue scatters into g_q/g_k/g_v with [B,H,L,DH] layout.
// ---------------------------------------------------------------------------
__global__ __launch_bounds__(256) void qkv_gemm_kernel(
    const float* __restrict__ x, const float* __restrict__ w)
{
    __shared__ float As[32][68];
    __shared__ float Bs[32][68];

    const int tid = threadIdx.x;
    const int tx  = tid & 15;
    const int ty  = tid >> 4;
    const int m0  = blockIdx.y * 64;
    const int n0  = blockIdx.x * 64;

    float acc[4][4] = {};

    for (int k0 = 0; k0 < DD; k0 += 32) {
        #pragma unroll
        for (int r = 0; r < 2; r++) {
            int row = (tid >> 3) + r * 32;   // 0..63
            int kq  = (tid & 7) * 4;         // 0..28
            float4 a = *(const float4*)&x[(size_t)(m0 + row) * DD + k0 + kq];
            As[kq + 0][row] = a.x; As[kq + 1][row] = a.y;
            As[kq + 2][row] = a.z; As[kq + 3][row] = a.w;
            float4 b = *(const float4*)&w[(size_t)(n0 + row) * DD + k0 + kq];
            Bs[kq + 0][row] = b.x; Bs[kq + 1][row] = b.y;
            Bs[kq + 2][row] = b.z; Bs[kq + 3][row] = b.w;
        }
        __syncthreads();

        #pragma unroll
        for (int k = 0; k < 32; k++) {
            float4 av = *(const float4*)&As[k][ty * 4];
            float4 bv = *(const float4*)&Bs[k][tx * 4];
            float aa[4] = {av.x, av.y, av.z, av.w};
            float bb[4] = {bv.x, bv.y, bv.z, bv.w};
            #pragma unroll
            for (int i = 0; i < 4; i++)
                #pragma unroll
                for (int j = 0; j < 4; j++)
                    acc[i][j] = fmaf(aa[i], bb[j], acc[i][j]);
        }
        __syncthreads();
    }

    // n-tile (64 wide, 64-aligned) maps to a single (which, head); dh = n & 63
    const int which = n0 >> 10;            // 0=q, 1=k, 2=v
    const int h     = (n0 & 1023) >> 6;    // head
    float* dst = (which == 0) ? g_q : (which == 1) ? g_k : g_v;

    #pragma unroll
    for (int i = 0; i < 4; i++) {
        int mrow = m0 + ty * 4 + i;        // = b*L + l
        int b    = mrow >> 11;             // L = 2048
        int l    = mrow & 2047;
        size_t base = (((size_t)(b * HH + h)) * LL + l) * DHH;
        #pragma unroll
        for (int j = 0; j < 4; j++) {
            int dh = tx * 4 + j;
            dst[base + dh] = acc[i][j];
        }
    }
}

// ---------------------------------------------------------------------------
// Kernel 2: Flash attention. One CTA = one (b,h) and 64 query rows.
// 256 threads (16x16), 4x4 micro-tiles, online softmax.
// smem: Qs/Ks d-major [64][68], Vs kk-major [64][68], Ps kk-major [64][68].
// ---------------------------------------------------------------------------
__global__ __launch_bounds__(256) void flash_kernel()
{
    extern __shared__ float sm[];
    float (*Qs)[68] = (float(*)[68])(sm);
    float (*Ks)[68] = (float(*)[68])(sm + 64 * 68);
    float (*Vs)[68] = (float(*)[68])(sm + 2 * 64 * 68);
    float (*Ps)[68] = (float(*)[68])(sm + 3 * 64 * 68);

    const int tid = threadIdx.x;
    const int tx  = tid & 15;
    const int ty  = tid >> 4;
    const int bh  = blockIdx.y;
    const int q0  = blockIdx.x * 64;

    const float* Qg = g_q + (size_t)bh * LL * DHH;
    const float* Kg = g_k + (size_t)bh * LL * DHH;
    const float* Vg = g_v + (size_t)bh * LL * DHH;

    const float scale = 0.125f;  // 1/sqrt(64)

    // Load Q tile transposed (d-major), scale folded in
    #pragma unroll
    for (int r = 0; r < 4; r++) {
        int qq = (tid >> 4) + r * 16;   // 0..63
        int dq = (tid & 15) * 4;        // 0..60
        float4 a = *(const float4*)&Qg[(size_t)(q0 + qq) * DHH + dq];
        Qs[dq + 0][qq] = a.x * scale;
        Qs[dq + 1][qq] = a.y * scale;
        Qs[dq + 2][qq] = a.z * scale;
        Qs[dq + 3][qq] = a.w * scale;
    }

    float o[4][4] = {};
    float mrow[4] = {-1e30f, -1e30f, -1e30f, -1e30f};
    float lrow[4] = {0.f, 0.f, 0.f, 0.f};

    for (int kb = 0; kb < LL; kb += 64) {
        __syncthreads();   // prev MM2 done before overwriting Ks/Vs
        #pragma unroll
        for (int r = 0; r < 4; r++) {
            int kk = (tid >> 4) + r * 16;
            int dq = (tid & 15) * 4;
            float4 a = *(const float4*)&Kg[(size_t)(kb + kk) * DHH + dq];
            Ks[dq + 0][kk] = a.x; Ks[dq + 1][kk] = a.y;
            Ks[dq + 2][kk] = a.z; Ks[dq + 3][kk] = a.w;
            float4 v4 = *(const float4*)&Vg[(size_t)(kb + kk) * DHH + dq];
            *(float4*)&Vs[kk][dq] = v4;
        }
        __syncthreads();

        // S = (Q*scale) K^T
        float s[4][4] = {};
        #pragma unroll
        for (int d = 0; d < 64; d++) {
            float4 qv = *(const float4*)&Qs[d][ty * 4];
            float4 kv = *(const float4*)&Ks[d][tx * 4];
            float qa[4] = {qv.x, qv.y, qv.z, qv.w};
            float ka[4] = {kv.x, kv.y, kv.z, kv.w};
            #pragma unroll
            for (int i = 0; i < 4; i++)
                #pragma unroll
                for (int j = 0; j < 4; j++)
                    s[i][j] = fmaf(qa[i], ka[j], s[i][j]);
        }

        // Online softmax (row reductions across the 16 tx lanes)
        #pragma unroll
        for (int i = 0; i < 4; i++) {
            float mx = fmaxf(fmaxf(s[i][0], s[i][1]), fmaxf(s[i][2], s[i][3]));
            #pragma unroll
            for (int off = 8; off; off >>= 1)
                mx = fmaxf(mx, __shfl_xor_sync(0xffffffffu, mx, off));
            float mnew = fmaxf(mrow[i], mx);
            float corr = __expf(mrow[i] - mnew);
            mrow[i] = mnew;
            float rs = 0.f;
            #pragma unroll
            for (int j = 0; j < 4; j++) {
                float p = __expf(s[i][j] - mnew);
                s[i][j] = p;
                rs += p;
            }
            #pragma unroll
            for (int off = 8; off; off >>= 1)
                rs += __shfl_xor_sync(0xffffffffu, rs, off);
            lrow[i] = lrow[i] * corr + rs;
            #pragma unroll
            for (int j = 0; j < 4; j++) o[i][j] *= corr;
        }

        // P -> smem transposed (kk-major)
        #pragma unroll
        for (int i = 0; i < 4; i++)
            #pragma unroll
            for (int j = 0; j < 4; j++)
                Ps[tx * 4 + j][ty * 4 + i] = s[i][j];
        __syncthreads();

        // O += P V
        #pragma unroll
        for (int kk = 0; kk < 64; kk++) {
            float4 pv = *(const float4*)&Ps[kk][ty * 4];
            float4 vv = *(const float4*)&Vs[kk][tx * 4];
            float pa[4] = {pv.x, pv.y, pv.z, pv.w};
            float va[4] = {vv.x, vv.y, vv.z, vv.w};
            #pragma unroll
            for (int i = 0; i < 4; i++)
                #pragma unroll
                for (int j = 0; j < 4; j++)
                    o[i][j] = fmaf(pa[i], va[j], o[i][j]);
        }
    }

    const int b = bh >> 4;
    const int h = bh & 15;
    #pragma unroll
    for (int i = 0; i < 4; i++) {
        float inv = 1.f / lrow[i];
        int gq = q0 + ty * 4 + i;
        size_t base = ((size_t)(b * LL + gq)) * DD + h * 64;
        #pragma unroll
        for (int j = 0; j < 4; j++)
            g_ctx[base + tx * 4 + j] = o[i][j] * inv;
    }
}

// ---------------------------------------------------------------------------
// Kernel 3: output projection  out[m,n] = sum_k ctx[m,k] * w_proj[n,k]
// M=8192, N=1024, K=1024. Same tiling as kernel 1, plain row-major store.
// ---------------------------------------------------------------------------
__global__ __launch_bounds__(256) void proj_gemm_kernel(
    const float* __restrict__ w, float* __restrict__ out)
{
    __shared__ float As[32][68];
    __shared__ float Bs[32][68];

    const int tid = threadIdx.x;
    const int tx  = tid & 15;
    const int ty  = tid >> 4;
    const int m0  = blockIdx.y * 64;
    const int n0  = blockIdx.x * 64;

    float acc[4][4] = {};

    for (int k0 = 0; k0 < DD; k0 += 32) {
        #pragma unroll
        for (int r = 0; r < 2; r++) {
            int row = (tid >> 3) + r * 32;
            int kq  = (tid & 7) * 4;
            float4 a = *(const float4*)&g_ctx[(size_t)(m0 + row) * DD + k0 + kq];
            As[kq + 0][row] = a.x; As[kq + 1][row] = a.y;
            As[kq + 2][row] = a.z; As[kq + 3][row] = a.w;
            float4 b = *(const float4*)&w[(size_t)(n0 + row) * DD + k0 + kq];
            Bs[kq + 0][row] = b.x; Bs[kq + 1][row] = b.y;
            Bs[kq + 2][row] = b.z; Bs[kq + 3][row] = b.w;
        }
        __syncthreads();

        #pragma unroll
        for (int k = 0; k < 32; k++) {
            float4 av = *(const float4*)&As[k][ty * 4];
            float4 bv = *(const float4*)&Bs[k][tx * 4];
            float aa[4] = {av.x, av.y, av.z, av.w};
            float bb[4] = {bv.x, bv.y, bv.z, bv.w};
            #pragma unroll
            for (int i = 0; i < 4; i++)
                #pragma unroll
                for (int j = 0; j < 4; j++)
                    acc[i][j] = fmaf(aa[i], bb[j], acc[i][j]);
        }
        __syncthreads();
    }

    #pragma unroll
    for (int i = 0; i < 4; i++) {
        int mrow = m0 + ty * 4 + i;
        #pragma unroll
        for (int j = 0; j < 4; j++)
            out[(size_t)mrow * DD + n0 + tx * 4 + j] = acc[i][j];
    }
}

extern "C" void kernel_launch(void* const* d_in, const int* in_sizes, int n_in,
                              void* d_out, int out_size)
{
    const float* x      = (const float*)d_in[0];
    const float* w_qkv  = (const float*)d_in[1];
    const float* w_proj = (const float*)d_in[2];
    float* out          = (float*)d_out;

    // QKV: N=3072 -> 48 tiles, M=8192 -> 128 tiles
    qkv_gemm_kernel<<<dim3(48, 128), 256>>>(x, w_qkv);

    const int flash_smem = 4 * 64 * 68 * (int)sizeof(float);  // 69,632 B
    cudaFuncSetAttribute(flash_kernel,
                         cudaFuncAttributeMaxDynamicSharedMemorySize, flash_smem);
    flash_kernel<<<dim3(LL / 64, BB * HH), 256, flash_smem>>>();

    // Proj: N=1024 -> 16 tiles
    proj_gemm_kernel<<<dim3(16, 128), 256>>>(w_proj, out);
}

// round 4
// speedup vs baseline: 1.4566x; 1.4566x over previous
#include <cuda_runtime.h>
#include <cuda_bf16.h>
#include <math.h>
#include <stdint.h>

#define BB 4
#define LL 2048
#define DD 1024
#define HH 16
#define DHH 64

// Scratch (allocation-free)
__device__ float g_qkv[(size_t)8192 * 3072];  // row-major [B*L, 3*D]
__device__ float g_ctx[(size_t)8192 * 1024];  // row-major [B*L, D]

__device__ __forceinline__ uint32_t smem_u32(const void* p) {
    uint32_t a;
    asm("{ .reg .u64 t; cvta.to.shared.u64 t, %1; cvt.u32.u64 %0, t; }"
        : "=r"(a) : "l"(p));
    return a;
}

__device__ __forceinline__ void ldsm_x4(uint32_t* r, uint32_t addr) {
    asm volatile("ldmatrix.sync.aligned.m8n8.x4.shared.b16 {%0,%1,%2,%3}, [%4];"
                 : "=r"(r[0]), "=r"(r[1]), "=r"(r[2]), "=r"(r[3]) : "r"(addr));
}

__device__ __forceinline__ void mma_bf16(float* d, const uint32_t* a,
                                         const uint32_t* b) {
    asm volatile(
        "mma.sync.aligned.m16n8k16.row.col.f32.bf16.bf16.f32 "
        "{%0,%1,%2,%3}, {%4,%5,%6,%7}, {%8,%9}, {%0,%1,%2,%3};"
        : "+f"(d[0]), "+f"(d[1]), "+f"(d[2]), "+f"(d[3])
        : "r"(a[0]), "r"(a[1]), "r"(a[2]), "r"(a[3]), "r"(b[0]), "r"(b[1]));
}

// ---------------------------------------------------------------------------
// HMMA 3x-bf16-split GEMM:  C[m,n] = sum_k A[m,k] * B[n,k]
// Tile 128x128x32, 256 threads (8 warps, 2x4), warp tile 64x32.
// A==nullptr -> g_ctx;  C==nullptr -> g_qkv. K fixed = 1024.
// ---------------------------------------------------------------------------
#define PITCH 40  // bf16 elements per smem row (80 bytes)

__global__ __launch_bounds__(256) void mma_gemm_kernel(
    const float* __restrict__ Ap, const float* __restrict__ Bp,
    float* __restrict__ Cp, int ldc)
{
    __shared__ __nv_bfloat16 Ah[128][PITCH];
    __shared__ __nv_bfloat16 Al[128][PITCH];
    __shared__ __nv_bfloat16 Bh[128][PITCH];
    __shared__ __nv_bfloat16 Bl[128][PITCH];

    const float* A = Ap ? Ap : g_ctx;
    const float* B = Bp;
    float* C = Cp ? Cp : g_qkv;

    const int tid  = threadIdx.x;
    const int wid  = tid >> 5;
    const int lane = tid & 31;
    const int m0   = blockIdx.y * 128;
    const int n0   = blockIdx.x * 128;
    const int wm   = (wid >> 2) * 64;   // warp m offset in tile
    const int wn   = (wid & 3) * 32;    // warp n offset in tile

    const uint32_t sAh = smem_u32(Ah), sAl = smem_u32(Al);
    const uint32_t sBh = smem_u32(Bh), sBl = smem_u32(Bl);

    // gmem load mapping: idx = r*256+tid -> row = idx>>3, c4 = idx&7
    const int lrow = tid >> 3;
    const int lc4  = tid & 7;

    float c[4][4][4] = {};   // [mt][nt][4]

    float4 ra[4], rb[4];
    #pragma unroll
    for (int r = 0; r < 4; r++) {
        ra[r] = *(const float4*)&A[(size_t)(m0 + lrow + r * 32) * 1024 + lc4 * 4];
        rb[r] = *(const float4*)&B[(size_t)(n0 + lrow + r * 32) * 1024 + lc4 * 4];
    }

    for (int ch = 0; ch < 32; ch++) {
        // convert current chunk regs -> smem hi/lo
        #pragma unroll
        for (int r = 0; r < 4; r++) {
            int row = lrow + r * 32;
            float vals[2][4] = {{ra[r].x, ra[r].y, ra[r].z, ra[r].w},
                                {rb[r].x, rb[r].y, rb[r].z, rb[r].w}};
            #pragma unroll
            for (int s = 0; s < 2; s++) {
                __nv_bfloat16 h[4], l[4];
                #pragma unroll
                for (int j = 0; j < 4; j++) {
                    h[j] = __float2bfloat16(vals[s][j]);
                    l[j] = __float2bfloat16(vals[s][j] - __bfloat162float(h[j]));
                }
                __nv_bfloat16* dh = s ? &Bh[row][lc4 * 4] : &Ah[row][lc4 * 4];
                __nv_bfloat16* dl = s ? &Bl[row][lc4 * 4] : &Al[row][lc4 * 4];
                *(__nv_bfloat162*)(dh)     = __nv_bfloat162(h[0], h[1]);
                *(__nv_bfloat162*)(dh + 2) = __nv_bfloat162(h[2], h[3]);
                *(__nv_bfloat162*)(dl)     = __nv_bfloat162(l[0], l[1]);
                *(__nv_bfloat162*)(dl + 2) = __nv_bfloat162(l[2], l[3]);
            }
        }
        __syncthreads();

        // prefetch next chunk
        if (ch + 1 < 32) {
            const int k0 = (ch + 1) * 32;
            #pragma unroll
            for (int r = 0; r < 4; r++) {
                ra[r] = *(const float4*)&A[(size_t)(m0 + lrow + r * 32) * 1024 + k0 + lc4 * 4];
                rb[r] = *(const float4*)&B[(size_t)(n0 + lrow + r * 32) * 1024 + k0 + lc4 * 4];
            }
        }

        #pragma unroll
        for (int ks = 0; ks < 2; ks++) {
            // ldmatrix address pieces
            const uint32_t arow = (uint32_t)(wm + (lane & 15));
            const uint32_t acol = (uint32_t)(ks * 32 + (lane >> 4) * 16);
            const uint32_t brow = (uint32_t)(wn + (lane & 15));

            uint32_t ah[4][4], al[4][4];
            #pragma unroll
            for (int mt = 0; mt < 4; mt++) {
                uint32_t off = (arow + mt * 16) * (PITCH * 2) + acol;
                ldsm_x4(ah[mt], sAh + off);
                ldsm_x4(al[mt], sAl + off);
            }
            uint32_t bh[4][2], bl[4][2];
            #pragma unroll
            for (int half = 0; half < 2; half++) {
                uint32_t r4h[4], r4l[4];
                uint32_t off = (brow + half * 16) * (PITCH * 2) + acol;
                ldsm_x4(r4h, sBh + off);
                ldsm_x4(r4l, sBl + off);
                bh[half * 2 + 0][0] = r4h[0]; bh[half * 2 + 0][1] = r4h[2];
                bh[half * 2 + 1][0] = r4h[1]; bh[half * 2 + 1][1] = r4h[3];
                bl[half * 2 + 0][0] = r4l[0]; bl[half * 2 + 0][1] = r4l[2];
                bl[half * 2 + 1][0] = r4l[1]; bl[half * 2 + 1][1] = r4l[3];
            }

            #pragma unroll
            for (int mt = 0; mt < 4; mt++)
                #pragma unroll
                for (int nt = 0; nt < 4; nt++) {
                    mma_bf16(c[mt][nt], ah[mt], bh[nt]);
                    mma_bf16(c[mt][nt], ah[mt], bl[nt]);
                    mma_bf16(c[mt][nt], al[mt], bh[nt]);
                }
        }
        __syncthreads();
    }

    // Epilogue: fragment layout -> gmem (float2 stores)
    const int erow = lane >> 2;
    const int ecol = (lane & 3) * 2;
    #pragma unroll
    for (int mt = 0; mt < 4; mt++)
        #pragma unroll
        for (int nt = 0; nt < 4; nt++) {
            int row = m0 + wm + mt * 16 + erow;
            int col = n0 + wn + nt * 8 + ecol;
            *(float2*)&C[(size_t)row * ldc + col] =
                make_float2(c[mt][nt][0], c[mt][nt][1]);
            *(float2*)&C[(size_t)(row + 8) * ldc + col] =
                make_float2(c[mt][nt][2], c[mt][nt][3]);
        }
}

// ---------------------------------------------------------------------------
// Flash attention (SIMT fp32). Reads g_qkv [B*L][3072]:
// q at col h*64, k at 1024+h*64, v at 2048+h*64. Writes g_ctx [B*L][1024].
// ---------------------------------------------------------------------------
__global__ __launch_bounds__(256) void flash_kernel()
{
    extern __shared__ char dynsmem[];
    float* sm = (float*)dynsmem;
    float (*Qs)[68] = (float(*)[68])(sm);
    float (*Ks)[68] = (float(*)[68])(sm + 64 * 68);
    float (*Vs)[68] = (float(*)[68])(sm + 2 * 64 * 68);
    float (*Ps)[68] = (float(*)[68])(sm + 3 * 64 * 68);

    const int tid = threadIdx.x;
    const int tx  = tid & 15;
    const int ty  = tid >> 4;
    const int bh  = blockIdx.y;
    const int q0  = blockIdx.x * 64;
    const int b   = bh >> 4;
    const int h   = bh & 15;

    const float* base = g_qkv + (size_t)(b * LL) * 3072 + h * 64;
    const float scale = 0.125f;

    #pragma unroll
    for (int r = 0; r < 4; r++) {
        int qq = (tid >> 4) + r * 16;
        int dq = (tid & 15) * 4;
        float4 a = *(const float4*)&base[(size_t)(q0 + qq) * 3072 + dq];
        Qs[dq + 0][qq] = a.x * scale;
        Qs[dq + 1][qq] = a.y * scale;
        Qs[dq + 2][qq] = a.z * scale;
        Qs[dq + 3][qq] = a.w * scale;
    }

    float o[4][4] = {};
    float mrow[4] = {-1e30f, -1e30f, -1e30f, -1e30f};
    float lrow[4] = {0.f, 0.f, 0.f, 0.f};

    for (int kb = 0; kb < LL; kb += 64) {
        __syncthreads();
        #pragma unroll
        for (int r = 0; r < 4; r++) {
            int kk = (tid >> 4) + r * 16;
            int dq = (tid & 15) * 4;
            float4 a = *(const float4*)&base[(size_t)(kb + kk) * 3072 + 1024 + dq];
            Ks[dq + 0][kk] = a.x; Ks[dq + 1][kk] = a.y;
            Ks[dq + 2][kk] = a.z; Ks[dq + 3][kk] = a.w;
            float4 v4 = *(const float4*)&base[(size_t)(kb + kk) * 3072 + 2048 + dq];
            *(float4*)&Vs[kk][dq] = v4;
        }
        __syncthreads();

        float s[4][4] = {};
        #pragma unroll
        for (int d = 0; d < 64; d++) {
            float4 qv = *(const float4*)&Qs[d][ty * 4];
            float4 kv = *(const float4*)&Ks[d][tx * 4];
            float qa[4] = {qv.x, qv.y, qv.z, qv.w};
            float ka[4] = {kv.x, kv.y, kv.z, kv.w};
            #pragma unroll
            for (int i = 0; i < 4; i++)
                #pragma unroll
                for (int j = 0; j < 4; j++)
                    s[i][j] = fmaf(qa[i], ka[j], s[i][j]);
        }

        #pragma unroll
        for (int i = 0; i < 4; i++) {
            float mx = fmaxf(fmaxf(s[i][0], s[i][1]), fmaxf(s[i][2], s[i][3]));
            #pragma unroll
            for (int off = 8; off; off >>= 1)
                mx = fmaxf(mx, __shfl_xor_sync(0xffffffffu, mx, off));
            float mnew = fmaxf(mrow[i], mx);
            float corr = __expf(mrow[i] - mnew);
            mrow[i] = mnew;
            float rs = 0.f;
            #pragma unroll
            for (int j = 0; j < 4; j++) {
                float p = __expf(s[i][j] - mnew);
                s[i][j] = p;
                rs += p;
            }
            #pragma unroll
            for (int off = 8; off; off >>= 1)
                rs += __shfl_xor_sync(0xffffffffu, rs, off);
            lrow[i] = lrow[i] * corr + rs;
            #pragma unroll
            for (int j = 0; j < 4; j++) o[i][j] *= corr;
        }

        #pragma unroll
        for (int i = 0; i < 4; i++)
            #pragma unroll
            for (int j = 0; j < 4; j++)
                Ps[tx * 4 + j][ty * 4 + i] = s[i][j];
        __syncthreads();

        #pragma unroll
        for (int kk = 0; kk < 64; kk++) {
            float4 pv = *(const float4*)&Ps[kk][ty * 4];
            float4 vv = *(const float4*)&Vs[kk][tx * 4];
            float pa[4] = {pv.x, pv.y, pv.z, pv.w};
            float va[4] = {vv.x, vv.y, vv.z, vv.w};
            #pragma unroll
            for (int i = 0; i < 4; i++)
                #pragma unroll
                for (int j = 0; j < 4; j++)
                    o[i][j] = fmaf(pa[i], va[j], o[i][j]);
        }
    }

    #pragma unroll
    for (int i = 0; i < 4; i++) {
        float inv = 1.f / lrow[i];
        int gq = q0 + ty * 4 + i;
        size_t obase = ((size_t)(b * LL + gq)) * DD + h * 64;
        #pragma unroll
        for (int j = 0; j < 4; j++)
            g_ctx[obase + tx * 4 + j] = o[i][j] * inv;
    }
}

extern "C" void kernel_launch(void* const* d_in, const int* in_sizes, int n_in,
                              void* d_out, int out_size)
{
    const float* x      = (const float*)d_in[0];
    const float* w_qkv  = (const float*)d_in[1];
    const float* w_proj = (const float*)d_in[2];
    float* out          = (float*)d_out;

    // QKV: M=8192, N=3072 -> grid (24, 64)
    mma_gemm_kernel<<<dim3(24, 64), 256>>>(x, w_qkv, nullptr, 3072);

    const int flash_smem = 4 * 64 * 68 * (int)sizeof(float);  // 69,632 B
    cudaFuncSetAttribute(flash_kernel,
                         cudaFuncAttributeMaxDynamicSharedMemorySize, flash_smem);
    flash_kernel<<<dim3(LL / 64, BB * HH), 256, flash_smem>>>();

    // Proj: M=8192, N=1024 -> grid (8, 64)
    mma_gemm_kernel<<<dim3(8, 64), 256>>>(nullptr, w_proj, out, 1024);
}

// round 5
// speedup vs baseline: 1.6421x; 1.1274x over previous
#include <cuda_runtime.h>
#include <cuda_bf16.h>
#include <math.h>
#include <stdint.h>

#define BB 4
#define LL 2048
#define DD 1024
#define HH 16
#define DHH 64

typedef __nv_bfloat16 bf16;

// ---------------- scratch (allocation-free device globals) ----------------
__device__ bf16 g_xh[(size_t)8192 * 1024], g_xl[(size_t)8192 * 1024];
__device__ bf16 g_wqh[(size_t)3072 * 1024], g_wql[(size_t)3072 * 1024];
__device__ bf16 g_wph[(size_t)1024 * 1024], g_wpl[(size_t)1024 * 1024];
__device__ bf16 g_qh[(size_t)64 * 2048 * 64], g_ql[(size_t)64 * 2048 * 64];
__device__ bf16 g_kh[(size_t)64 * 2048 * 64], g_kl[(size_t)64 * 2048 * 64];
__device__ bf16 g_vh[(size_t)64 * 2048 * 64], g_vl[(size_t)64 * 2048 * 64];
__device__ bf16 g_ctxh[(size_t)8192 * 1024], g_ctxl[(size_t)8192 * 1024];

// ---------------- PTX helpers ----------------
__device__ __forceinline__ uint32_t smem_u32(const void* p) {
    uint32_t a;
    asm("{ .reg .u64 t; cvta.to.shared.u64 t, %1; cvt.u32.u64 %0, t; }"
        : "=r"(a) : "l"(p));
    return a;
}
__device__ __forceinline__ void ldsm_x4(uint32_t* r, uint32_t addr) {
    asm volatile("ldmatrix.sync.aligned.m8n8.x4.shared.b16 {%0,%1,%2,%3}, [%4];"
                 : "=r"(r[0]), "=r"(r[1]), "=r"(r[2]), "=r"(r[3]) : "r"(addr));
}
__device__ __forceinline__ void ldsm_x4_t(uint32_t* r, uint32_t addr) {
    asm volatile("ldmatrix.sync.aligned.m8n8.x4.trans.shared.b16 {%0,%1,%2,%3}, [%4];"
                 : "=r"(r[0]), "=r"(r[1]), "=r"(r[2]), "=r"(r[3]) : "r"(addr));
}
__device__ __forceinline__ void mma_bf16(float* d, const uint32_t* a,
                                         const uint32_t* b) {
    asm volatile(
        "mma.sync.aligned.m16n8k16.row.col.f32.bf16.bf16.f32 "
        "{%0,%1,%2,%3}, {%4,%5,%6,%7}, {%8,%9}, {%0,%1,%2,%3};"
        : "+f"(d[0]), "+f"(d[1]), "+f"(d[2]), "+f"(d[3])
        : "r"(a[0]), "r"(a[1]), "r"(a[2]), "r"(a[3]), "r"(b[0]), "r"(b[1]));
}
#define CP_ASYNC16(dst, src) \
    asm volatile("cp.async.cg.shared.global [%0], [%1], 16;" \
                 :: "r"(dst), "l"(src) : "memory")
#define CP_COMMIT() asm volatile("cp.async.commit_group;" ::: "memory")
#define CP_WAIT0()  asm volatile("cp.async.wait_group 0;" ::: "memory")

__device__ __forceinline__ uint32_t pack_bf16x2(float a, float b) {
    __nv_bfloat162 t = __floats2bfloat162_rn(a, b);
    return *(uint32_t*)&t;
}
__device__ __forceinline__ void split_bf16(float v, bf16& h, bf16& l) {
    h = __float2bfloat16(v);
    l = __float2bfloat16(v - __bfloat162float(h));
}

// ---------------------------------------------------------------------------
// conv_split: fp32 -> (hi, lo) bf16, elementwise
// ---------------------------------------------------------------------------
__global__ void conv_split(const float* __restrict__ src, bf16* __restrict__ h,
                           bf16* __restrict__ l, int n4)
{
    int i = blockIdx.x * blockDim.x + threadIdx.x;
    if (i >= n4) return;
    float4 v = ((const float4*)src)[i];
    bf16 h0, l0, h1, l1, h2, l2, h3, l3;
    split_bf16(v.x, h0, l0); split_bf16(v.y, h1, l1);
    split_bf16(v.z, h2, l2); split_bf16(v.w, h3, l3);
    ((__nv_bfloat162*)h)[2 * i]     = __nv_bfloat162(h0, h1);
    ((__nv_bfloat162*)h)[2 * i + 1] = __nv_bfloat162(h2, h3);
    ((__nv_bfloat162*)l)[2 * i]     = __nv_bfloat162(l0, l1);
    ((__nv_bfloat162*)l)[2 * i + 1] = __nv_bfloat162(l2, l3);
}

// ---------------------------------------------------------------------------
// HMMA GEMM on pre-split bf16:  C[m,n] = sum_k A[m,k]*B[n,k], K=1024.
// Tile 128x128x32, 8 warps (2x4), warp 64x32, cp.async double buffer.
// mode 0: QKV epilogue -> scatter bf16 hi/lo into g_q/g_k/g_v (q scaled).
// mode 1: fp32 epilogue -> Cp (ldc).
// smem: 2 stages x (Ah|Al|Bh|Bl), each 128 rows x 40 bf16 (80B pitch).
// ---------------------------------------------------------------------------
#define GP 40                     // gemm smem pitch (bf16 elems), 80 B
#define GMAT (128 * GP * 2)       // 10240 B per matrix
#define GSTAGE (4 * GMAT)         // 40960 B per stage
#define GEMM_SMEM (2 * GSTAGE)    // 81920 B

__global__ __launch_bounds__(256) void hmma_gemm(
    const bf16* __restrict__ Ah_g, const bf16* __restrict__ Al_g,
    const bf16* __restrict__ Bh_g, const bf16* __restrict__ Bl_g,
    float* __restrict__ Cp, int ldc, int mode)
{
    extern __shared__ char smem[];
    const uint32_t sb = smem_u32(smem);

    const int tid  = threadIdx.x;
    const int wid  = tid >> 5;
    const int lane = tid & 31;
    const int m0   = blockIdx.y * 128;
    const int n0   = blockIdx.x * 128;
    const int wm   = (wid >> 2) * 64;
    const int wn   = (wid & 3) * 32;

    const bf16* mats[4] = {Ah_g, Al_g, Bh_g, Bl_g};

    float c[4][4][4] = {};

    // issue chunk 0
    {
        const int k0 = 0;
        #pragma unroll
        for (int it = 0; it < 8; it++) {
            int i = tid + it * 256;
            int mat = i >> 9, r = (i >> 2) & 127, part = i & 3;
            const bf16* g = mats[mat];
            int grow = (mat < 2) ? (m0 + r) : (n0 + r);
            const bf16* src = g + (size_t)grow * 1024 + k0 + part * 8;
            uint32_t dst = sb + mat * GMAT + r * (GP * 2) + part * 16;
            CP_ASYNC16(dst, src);
        }
        CP_COMMIT();
    }

    for (int ch = 0; ch < 32; ch++) {
        CP_WAIT0();
        __syncthreads();

        if (ch + 1 < 32) {
            const int k0 = (ch + 1) * 32;
            const uint32_t stg = sb + ((ch + 1) & 1) * GSTAGE;
            #pragma unroll
            for (int it = 0; it < 8; it++) {
                int i = tid + it * 256;
                int mat = i >> 9, r = (i >> 2) & 127, part = i & 3;
                const bf16* g = mats[mat];
                int grow = (mat < 2) ? (m0 + r) : (n0 + r);
                const bf16* src = g + (size_t)grow * 1024 + k0 + part * 8;
                uint32_t dst = stg + mat * GMAT + r * (GP * 2) + part * 16;
                CP_ASYNC16(dst, src);
            }
            CP_COMMIT();
        }

        const uint32_t stg = sb + (ch & 1) * GSTAGE;
        const uint32_t sAh = stg, sAl = stg + GMAT;
        const uint32_t sBh = stg + 2 * GMAT, sBl = stg + 3 * GMAT;

        #pragma unroll
        for (int ks = 0; ks < 2; ks++) {
            const uint32_t kc = (uint32_t)(ks * 32 + (lane >> 4) * 16);
            uint32_t ah[4][4], al[4][4];
            #pragma unroll
            for (int mt = 0; mt < 4; mt++) {
                uint32_t off = (uint32_t)(wm + mt * 16 + (lane & 15)) * (GP * 2) + kc;
                ldsm_x4(ah[mt], sAh + off);
                ldsm_x4(al[mt], sAl + off);
            }
            uint32_t bh[4][2], bl[4][2];
            #pragma unroll
            for (int half = 0; half < 2; half++) {
                uint32_t r4h[4], r4l[4];
                uint32_t off = (uint32_t)(wn + half * 16 + (lane & 15)) * (GP * 2) + kc;
                ldsm_x4(r4h, sBh + off);
                ldsm_x4(r4l, sBl + off);
                bh[half * 2 + 0][0] = r4h[0]; bh[half * 2 + 0][1] = r4h[2];
                bh[half * 2 + 1][0] = r4h[1]; bh[half * 2 + 1][1] = r4h[3];
                bl[half * 2 + 0][0] = r4l[0]; bl[half * 2 + 0][1] = r4l[2];
                bl[half * 2 + 1][0] = r4l[1]; bl[half * 2 + 1][1] = r4l[3];
            }
            #pragma unroll
            for (int mt = 0; mt < 4; mt++)
                #pragma unroll
                for (int nt = 0; nt < 4; nt++) {
                    mma_bf16(c[mt][nt], ah[mt], bh[nt]);
                    mma_bf16(c[mt][nt], ah[mt], bl[nt]);
                    mma_bf16(c[mt][nt], al[mt], bh[nt]);
                }
        }
        __syncthreads();
    }

    const int erow = lane >> 2;
    const int ecol = (lane & 3) * 2;

    if (mode == 1) {
        #pragma unroll
        for (int mt = 0; mt < 4; mt++)
            #pragma unroll
            for (int nt = 0; nt < 4; nt++) {
                int row = m0 + wm + mt * 16 + erow;
                int col = n0 + wn + nt * 8 + ecol;
                *(float2*)&Cp[(size_t)row * ldc + col] =
                    make_float2(c[mt][nt][0], c[mt][nt][1]);
                *(float2*)&Cp[(size_t)(row + 8) * ldc + col] =
                    make_float2(c[mt][nt][2], c[mt][nt][3]);
            }
    } else {
        // scatter to q/k/v hi/lo, [B*H][L][64]; q pre-scaled by 1/8
        const int which = n0 >> 10;
        bf16* dsth = (which == 0) ? g_qh : (which == 1) ? g_kh : g_vh;
        bf16* dstl = (which == 0) ? g_ql : (which == 1) ? g_kl : g_vl;
        const float sc = (which == 0) ? 0.125f : 1.0f;
        #pragma unroll
        for (int mt = 0; mt < 4; mt++)
            #pragma unroll
            for (int nt = 0; nt < 4; nt++) {
                int col = (n0 & 1023) + wn + nt * 8 + ecol;
                int h = col >> 6, dh = col & 63;
                #pragma unroll
                for (int rr = 0; rr < 2; rr++) {
                    int row = m0 + wm + mt * 16 + erow + rr * 8;
                    int b = row >> 11, l = row & 2047;
                    size_t base = ((size_t)((b << 4) + h) * 2048 + l) * 64 + dh;
                    float v0 = c[mt][nt][rr * 2 + 0] * sc;
                    float v1 = c[mt][nt][rr * 2 + 1] * sc;
                    bf16 h0, l0, h1, l1;
                    split_bf16(v0, h0, l0);
                    split_bf16(v1, h1, l1);
                    *(__nv_bfloat162*)(dsth + base) = __nv_bfloat162(h0, h1);
                    *(__nv_bfloat162*)(dstl + base) = __nv_bfloat162(l0, l1);
                }
            }
    }
}

// ---------------------------------------------------------------------------
// Flash attention, HMMA. CTA = 128 queries of one (b,h); 8 warps, warp = 16 rows.
// K/V tiles (64 keys) cp.async double-buffered. 3-term bf16 split both MMAs.
// smem: Qh|Ql (128x72 bf16, 144B pitch), 2 stages x (Kh|Kl|Vh|Vl) 64x72.
// ---------------------------------------------------------------------------
#define FP 72                       // flash smem pitch (bf16 elems), 144 B
#define FQ (128 * FP * 2)           // 18432 B per Q matrix
#define FMAT (64 * FP * 2)          // 9216 B per K/V matrix
#define FSTAGE (4 * FMAT)           // 36864 B
#define FLASH_SMEM (2 * FQ + 2 * FSTAGE)  // 110592 B

__global__ __launch_bounds__(256) void flash_hmma()
{
    extern __shared__ char smem[];
    const uint32_t sb = smem_u32(smem);
    const uint32_t sQh = sb, sQl = sb + FQ;
    const uint32_t sKV = sb + 2 * FQ;

    const int tid  = threadIdx.x;
    const int wid  = tid >> 5;
    const int lane = tid & 31;
    const int bh   = blockIdx.y;
    const int q0   = blockIdx.x * 128;
    const int b    = bh >> 4;
    const int h    = bh & 15;

    const bf16* kvg[4] = {g_kh + (size_t)bh * 2048 * 64, g_kl + (size_t)bh * 2048 * 64,
                          g_vh + (size_t)bh * 2048 * 64, g_vl + (size_t)bh * 2048 * 64};

    // Q tile -> smem (hi/lo)
    {
        const bf16* qh_g = g_qh + (size_t)bh * 2048 * 64;
        const bf16* ql_g = g_ql + (size_t)bh * 2048 * 64;
        #pragma unroll
        for (int it = 0; it < 4; it++) {
            int i = tid + it * 256;
            int r = i >> 3, part = i & 7;
            uint4 v = *(const uint4*)(qh_g + (size_t)(q0 + r) * 64 + part * 8);
            *(uint4*)(smem + r * (FP * 2) + part * 16) = v;
            uint4 w = *(const uint4*)(ql_g + (size_t)(q0 + r) * 64 + part * 8);
            *(uint4*)(smem + FQ + r * (FP * 2) + part * 16) = w;
        }
    }

    // issue K/V block 0 -> stage 0
    #pragma unroll
    for (int it = 0; it < 8; it++) {
        int i = tid + it * 256;
        int mat = i >> 9, r = (i >> 3) & 63, part = i & 7;
        const bf16* src = kvg[mat] + (size_t)r * 64 + part * 8;
        uint32_t dst = sKV + mat * FMAT + r * (FP * 2) + part * 16;
        CP_ASYNC16(dst, src);
    }
    CP_COMMIT();
    __syncthreads();

    // Q fragments (held in registers for the whole kernel)
    uint32_t qh[4][4], ql[4][4];
    #pragma unroll
    for (int ks = 0; ks < 4; ks++) {
        uint32_t off = (uint32_t)(wid * 16 + (lane & 15)) * (FP * 2)
                     + ks * 32 + (lane >> 4) * 16;
        ldsm_x4(qh[ks], sQh + off);
        ldsm_x4(ql[ks], sQl + off);
    }

    float o[8][4] = {};
    float mrow[2] = {-1e30f, -1e30f};
    float lrow[2] = {0.f, 0.f};

    for (int kb = 0; kb < 32; kb++) {
        CP_WAIT0();
        __syncthreads();

        if (kb + 1 < 32) {
            const uint32_t stg = sKV + ((kb + 1) & 1) * FSTAGE;
            const int krow0 = (kb + 1) * 64;
            #pragma unroll
            for (int it = 0; it < 8; it++) {
                int i = tid + it * 256;
                int mat = i >> 9, r = (i >> 3) & 63, part = i & 7;
                const bf16* src = kvg[mat] + (size_t)(krow0 + r) * 64 + part * 8;
                uint32_t dst = stg + mat * FMAT + r * (FP * 2) + part * 16;
                CP_ASYNC16(dst, src);
            }
            CP_COMMIT();
        }

        const uint32_t stg = sKV + (kb & 1) * FSTAGE;
        const uint32_t sKh = stg, sKl = stg + FMAT;
        const uint32_t sVh = stg + 2 * FMAT, sVl = stg + 3 * FMAT;

        // ---- MMA1: S = Q K^T ----
        float s[8][4] = {};
        #pragma unroll
        for (int ks = 0; ks < 4; ks++) {
            const uint32_t kc = (uint32_t)(ks * 32 + (lane >> 4) * 16);
            #pragma unroll
            for (int p = 0; p < 4; p++) {
                uint32_t kh4[4], kl4[4];
                uint32_t off = (uint32_t)(p * 16 + (lane & 15)) * (FP * 2) + kc;
                ldsm_x4(kh4, sKh + off);
                ldsm_x4(kl4, sKl + off);
                uint32_t b0h[2] = {kh4[0], kh4[2]}, b1h[2] = {kh4[1], kh4[3]};
                uint32_t b0l[2] = {kl4[0], kl4[2]}, b1l[2] = {kl4[1], kl4[3]};
                mma_bf16(s[2 * p],     qh[ks], b0h);
                mma_bf16(s[2 * p],     qh[ks], b0l);
                mma_bf16(s[2 * p],     ql[ks], b0h);
                mma_bf16(s[2 * p + 1], qh[ks], b1h);
                mma_bf16(s[2 * p + 1], qh[ks], b1l);
                mma_bf16(s[2 * p + 1], ql[ks], b1h);
            }
        }

        // ---- online softmax ----
        #pragma unroll
        for (int rh = 0; rh < 2; rh++) {
            float mx = -1e30f;
            #pragma unroll
            for (int nt = 0; nt < 8; nt++)
                mx = fmaxf(mx, fmaxf(s[nt][2 * rh], s[nt][2 * rh + 1]));
            mx = fmaxf(mx, __shfl_xor_sync(0xffffffffu, mx, 1));
            mx = fmaxf(mx, __shfl_xor_sync(0xffffffffu, mx, 2));
            float mnew = fmaxf(mrow[rh], mx);
            float corr = __expf(mrow[rh] - mnew);
            mrow[rh] = mnew;
            float rs = 0.f;
            #pragma unroll
            for (int nt = 0; nt < 8; nt++) {
                float p0 = __expf(s[nt][2 * rh] - mnew);
                float p1 = __expf(s[nt][2 * rh + 1] - mnew);
                s[nt][2 * rh] = p0;
                s[nt][2 * rh + 1] = p1;
                rs += p0 + p1;
            }
            rs += __shfl_xor_sync(0xffffffffu, rs, 1);
            rs += __shfl_xor_sync(0xffffffffu, rs, 2);
            lrow[rh] = lrow[rh] * corr + rs;
            #pragma unroll
            for (int nt = 0; nt < 8; nt++) {
                o[nt][2 * rh]     *= corr;
                o[nt][2 * rh + 1] *= corr;
            }
        }

        // ---- P -> bf16 hi/lo A-fragments ----
        uint32_t ph[4][4], pl[4][4];
        #pragma unroll
        for (int ks = 0; ks < 4; ks++) {
            #pragma unroll
            for (int half = 0; half < 2; half++) {
                const float* sv = s[2 * ks + half];
                #pragma unroll
                for (int rr = 0; rr < 2; rr++) {
                    float v0 = sv[2 * rr], v1 = sv[2 * rr + 1];
                    bf16 h0, l0, h1, l1;
                    split_bf16(v0, h0, l0);
                    split_bf16(v1, h1, l1);
                    ph[ks][half * 2 + rr] = pack_bf16x2(__bfloat162float(h0),
                                                        __bfloat162float(h1));
                    pl[ks][half * 2 + rr] = pack_bf16x2(__bfloat162float(l0),
                                                        __bfloat162float(l1));
                }
            }
        }

        // ---- MMA2: O += P V  (V via ldmatrix.trans) ----
        #pragma unroll
        for (int ks = 0; ks < 4; ks++) {
            #pragma unroll
            for (int p = 0; p < 4; p++) {
                uint32_t vh4[4], vl4[4];
                uint32_t off = (uint32_t)(ks * 16 + (lane & 15)) * (FP * 2)
                             + p * 32 + (lane >> 4) * 16;
                ldsm_x4_t(vh4, sVh + off);
                ldsm_x4_t(vl4, sVl + off);
                uint32_t b0h[2] = {vh4[0], vh4[1]}, b1h[2] = {vh4[2], vh4[3]};
                uint32_t b0l[2] = {vl4[0], vl4[1]}, b1l[2] = {vl4[2], vl4[3]};
                mma_bf16(o[2 * p],     ph[ks], b0h);
                mma_bf16(o[2 * p],     ph[ks], b0l);
                mma_bf16(o[2 * p],     pl[ks], b0h);
                mma_bf16(o[2 * p + 1], ph[ks], b1h);
                mma_bf16(o[2 * p + 1], ph[ks], b1l);
                mma_bf16(o[2 * p + 1], pl[ks], b1h);
            }
        }
    }

    // ---- epilogue: normalize, split, store ctx hi/lo ----
    const int erow = lane >> 2;
    const int ecol = (lane & 3) * 2;
    #pragma unroll
    for (int rh = 0; rh < 2; rh++) {
        float inv = 1.f / lrow[rh];
        int row = q0 + wid * 16 + erow + rh * 8;
        size_t rbase = (size_t)(b * 2048 + row) * 1024 + h * 64;
        #pragma unroll
        for (int nt = 0; nt < 8; nt++) {
            float v0 = o[nt][2 * rh] * inv;
            float v1 = o[nt][2 * rh + 1] * inv;
            bf16 h0, l0, h1, l1;
            split_bf16(v0, h0, l0);
            split_bf16(v1, h1, l1);
            size_t idx = rbase + nt * 8 + ecol;
            *(__nv_bfloat162*)(g_ctxh + idx) = __nv_bfloat162(h0, h1);
            *(__nv_bfloat162*)(g_ctxl + idx) = __nv_bfloat162(l0, l1);
        }
    }
}

// ---------------------------------------------------------------------------
extern "C" void kernel_launch(void* const* d_in, const int* in_sizes, int n_in,
                              void* d_out, int out_size)
{
    const float* x      = (const float*)d_in[0];
    const float* w_qkv  = (const float*)d_in[1];
    const float* w_proj = (const float*)d_in[2];
    float* out          = (float*)d_out;

    bf16 *xh, *xl, *wqh, *wql, *wph, *wpl, *ctxh, *ctxl;
    cudaGetSymbolAddress((void**)&xh, g_xh);
    cudaGetSymbolAddress((void**)&xl, g_xl);
    cudaGetSymbolAddress((void**)&wqh, g_wqh);
    cudaGetSymbolAddress((void**)&wql, g_wql);
    cudaGetSymbolAddress((void**)&wph, g_wph);
    cudaGetSymbolAddress((void**)&wpl, g_wpl);
    cudaGetSymbolAddress((void**)&ctxh, g_ctxh);
    cudaGetSymbolAddress((void**)&ctxl, g_ctxl);

    // split inputs to bf16 hi/lo
    conv_split<<<(8192 * 1024 / 4 + 255) / 256, 256>>>(x, xh, xl, 8192 * 1024 / 4);
    conv_split<<<(3072 * 1024 / 4 + 255) / 256, 256>>>(w_qkv, wqh, wql, 3072 * 1024 / 4);
    conv_split<<<(1024 * 1024 / 4 + 255) / 256, 256>>>(w_proj, wph, wpl, 1024 * 1024 / 4);

    cudaFuncSetAttribute(hmma_gemm,
                         cudaFuncAttributeMaxDynamicSharedMemorySize, GEMM_SMEM);
    cudaFuncSetAttribute(flash_hmma,
                         cudaFuncAttributeMaxDynamicSharedMemorySize, FLASH_SMEM);

    // QKV: M=8192 N=3072
    hmma_gemm<<<dim3(24, 64), 256, GEMM_SMEM>>>(xh, xl, wqh, wql, nullptr, 0, 0);

    // flash: 16 q-tiles x 64 (b,h)
    flash_hmma<<<dim3(16, 64), 256, FLASH_SMEM>>>();

    // proj: M=8192 N=1024
    hmma_gemm<<<dim3(8, 64), 256, GEMM_SMEM>>>(ctxh, ctxl, wph, wpl, out, 1024, 1);
}

// round 6
// speedup vs baseline: 2.6438x; 1.6100x over previous
#include <cuda_runtime.h>
#include <cuda_bf16.h>
#include <math.h>
#include <stdint.h>

#define BB 4
#define LL 2048
#define DD 1024
#define HH 16
#define DHH 64

typedef __nv_bfloat16 bf16;

// ---------------- scratch (allocation-free device globals) ----------------
__device__ bf16 g_xh[(size_t)8192 * 1024], g_xl[(size_t)8192 * 1024];
__device__ bf16 g_wqh[(size_t)3072 * 1024], g_wql[(size_t)3072 * 1024];
__device__ bf16 g_wph[(size_t)1024 * 1024], g_wpl[(size_t)1024 * 1024];
__device__ bf16 g_qh[(size_t)64 * 2048 * 64], g_ql[(size_t)64 * 2048 * 64];
__device__ bf16 g_kh[(size_t)64 * 2048 * 64], g_kl[(size_t)64 * 2048 * 64];
__device__ bf16 g_vh[(size_t)64 * 2048 * 64], g_vl[(size_t)64 * 2048 * 64];
__device__ bf16 g_ctxh[(size_t)8192 * 1024], g_ctxl[(size_t)8192 * 1024];

// ---------------- PTX helpers ----------------
__device__ __forceinline__ uint32_t smem_u32(const void* p) {
    uint32_t a;
    asm("{ .reg .u64 t; cvta.to.shared.u64 t, %1; cvt.u32.u64 %0, t; }"
        : "=r"(a) : "l"(p));
    return a;
}
__device__ __forceinline__ void ldsm_x4(uint32_t* r, uint32_t addr) {
    asm volatile("ldmatrix.sync.aligned.m8n8.x4.shared.b16 {%0,%1,%2,%3}, [%4];"
                 : "=r"(r[0]), "=r"(r[1]), "=r"(r[2]), "=r"(r[3]) : "r"(addr));
}
__device__ __forceinline__ void ldsm_x4_t(uint32_t* r, uint32_t addr) {
    asm volatile("ldmatrix.sync.aligned.m8n8.x4.trans.shared.b16 {%0,%1,%2,%3}, [%4];"
                 : "=r"(r[0]), "=r"(r[1]), "=r"(r[2]), "=r"(r[3]) : "r"(addr));
}
__device__ __forceinline__ void mma_bf16(float* d, const uint32_t* a,
                                         const uint32_t* b) {
    asm volatile(
        "mma.sync.aligned.m16n8k16.row.col.f32.bf16.bf16.f32 "
        "{%0,%1,%2,%3}, {%4,%5,%6,%7}, {%8,%9}, {%0,%1,%2,%3};"
        : "+f"(d[0]), "+f"(d[1]), "+f"(d[2]), "+f"(d[3])
        : "r"(a[0]), "r"(a[1]), "r"(a[2]), "r"(a[3]), "r"(b[0]), "r"(b[1]));
}
#define CP_ASYNC16(dst, src) \
    asm volatile("cp.async.cg.shared.global [%0], [%1], 16;" \
                 :: "r"(dst), "l"(src) : "memory")
#define CP_COMMIT() asm volatile("cp.async.commit_group;" ::: "memory")
#define CP_WAIT0()  asm volatile("cp.async.wait_group 0;" ::: "memory")

__device__ __forceinline__ uint32_t pack_bf16x2(float a, float b) {
    __nv_bfloat162 t = __floats2bfloat162_rn(a, b);
    return *(uint32_t*)&t;
}
__device__ __forceinline__ void split_bf16(float v, bf16& h, bf16& l) {
    h = __float2bfloat16(v);
    l = __float2bfloat16(v - __bfloat162float(h));
}

// ---------------------------------------------------------------------------
// conv_split: fp32 -> (hi, lo) bf16, elementwise
// ---------------------------------------------------------------------------
__global__ void conv_split(const float* __restrict__ src, bf16* __restrict__ h,
                           bf16* __restrict__ l, int n4)
{
    int i = blockIdx.x * blockDim.x + threadIdx.x;
    if (i >= n4) return;
    float4 v = ((const float4*)src)[i];
    bf16 h0, l0, h1, l1, h2, l2, h3, l3;
    split_bf16(v.x, h0, l0); split_bf16(v.y, h1, l1);
    split_bf16(v.z, h2, l2); split_bf16(v.w, h3, l3);
    ((__nv_bfloat162*)h)[2 * i]     = __nv_bfloat162(h0, h1);
    ((__nv_bfloat162*)h)[2 * i + 1] = __nv_bfloat162(h2, h3);
    ((__nv_bfloat162*)l)[2 * i]     = __nv_bfloat162(l0, l1);
    ((__nv_bfloat162*)l)[2 * i + 1] = __nv_bfloat162(l2, l3);
}

// ---------------------------------------------------------------------------
// HMMA GEMM on pre-split bf16 (R4 register-prefetch structure):
// C[m,n] = sum_k A[m,k]*B[n,k], K=1024. Tile 128x128x32, 8 warps (2x4),
// warp 64x32, LDG uint4 prefetch -> static smem, ldmatrix + 3x mma passes.
// mode 0: scatter bf16 hi/lo into g_q/g_k/g_v (q scaled). mode 1: fp32 -> Cp.
// ---------------------------------------------------------------------------
#define GP 40  // smem pitch in bf16 elems (80 B): conflict-free ldmatrix

__global__ __launch_bounds__(256) void hmma_gemm(
    const bf16* __restrict__ Ah_g, const bf16* __restrict__ Al_g,
    const bf16* __restrict__ Bh_g, const bf16* __restrict__ Bl_g,
    float* __restrict__ Cp, int ldc, int mode)
{
    __shared__ bf16 Ah[128][GP], Al[128][GP], Bh[128][GP], Bl[128][GP];

    const int tid  = threadIdx.x;
    const int wid  = tid >> 5;
    const int lane = tid & 31;
    const int m0   = blockIdx.y * 128;
    const int n0   = blockIdx.x * 128;
    const int wm   = (wid >> 2) * 64;
    const int wn   = (wid & 3) * 32;

    const uint32_t sAh = smem_u32(Ah), sAl = smem_u32(Al);
    const uint32_t sBh = smem_u32(Bh), sBl = smem_u32(Bl);

    const bf16* mats[4] = {Ah_g, Al_g, Bh_g, Bl_g};
    bf16* smats[4] = {&Ah[0][0], &Al[0][0], &Bh[0][0], &Bl[0][0]};

    // load mapping: per matrix 512 16B-segments; idx = it*256+tid (it<2)
    // row = idx>>2 (0..127), part = idx&3 (16B each; 64B per row)
    float c[4][4][4] = {};
    uint4 pre[4][2];

    #pragma unroll
    for (int mat = 0; mat < 4; mat++)
        #pragma unroll
        for (int it = 0; it < 2; it++) {
            int idx = it * 256 + tid;
            int row = idx >> 2, part = idx & 3;
            int grow = (mat < 2) ? (m0 + row) : (n0 + row);
            pre[mat][it] = *(const uint4*)(mats[mat] + (size_t)grow * 1024 + part * 8);
        }

    for (int ch = 0; ch < 32; ch++) {
        // store prefetched chunk to smem
        #pragma unroll
        for (int mat = 0; mat < 4; mat++)
            #pragma unroll
            for (int it = 0; it < 2; it++) {
                int idx = it * 256 + tid;
                int row = idx >> 2, part = idx & 3;
                *(uint4*)(smats[mat] + row * GP + part * 8) = pre[mat][it];
            }
        __syncthreads();

        // prefetch next chunk (LDGs hidden under the MMA block below)
        if (ch + 1 < 32) {
            const int k0 = (ch + 1) * 32;
            #pragma unroll
            for (int mat = 0; mat < 4; mat++)
                #pragma unroll
                for (int it = 0; it < 2; it++) {
                    int idx = it * 256 + tid;
                    int row = idx >> 2, part = idx & 3;
                    int grow = (mat < 2) ? (m0 + row) : (n0 + row);
                    pre[mat][it] = *(const uint4*)(mats[mat] + (size_t)grow * 1024
                                                   + k0 + part * 8);
                }
        }

        #pragma unroll
        for (int ks = 0; ks < 2; ks++) {
            const uint32_t kc = (uint32_t)(ks * 32 + (lane >> 4) * 16);
            uint32_t ah[4][4], al[4][4];
            #pragma unroll
            for (int mt = 0; mt < 4; mt++) {
                uint32_t off = (uint32_t)(wm + mt * 16 + (lane & 15)) * (GP * 2) + kc;
                ldsm_x4(ah[mt], sAh + off);
                ldsm_x4(al[mt], sAl + off);
            }
            uint32_t bh[4][2], bl[4][2];
            #pragma unroll
            for (int half = 0; half < 2; half++) {
                uint32_t r4h[4], r4l[4];
                uint32_t off = (uint32_t)(wn + half * 16 + (lane & 15)) * (GP * 2) + kc;
                ldsm_x4(r4h, sBh + off);
                ldsm_x4(r4l, sBl + off);
                bh[half * 2 + 0][0] = r4h[0]; bh[half * 2 + 0][1] = r4h[2];
                bh[half * 2 + 1][0] = r4h[1]; bh[half * 2 + 1][1] = r4h[3];
                bl[half * 2 + 0][0] = r4l[0]; bl[half * 2 + 0][1] = r4l[2];
                bl[half * 2 + 1][0] = r4l[1]; bl[half * 2 + 1][1] = r4l[3];
            }
            #pragma unroll
            for (int mt = 0; mt < 4; mt++)
                #pragma unroll
                for (int nt = 0; nt < 4; nt++) {
                    mma_bf16(c[mt][nt], ah[mt], bh[nt]);
                    mma_bf16(c[mt][nt], ah[mt], bl[nt]);
                    mma_bf16(c[mt][nt], al[mt], bh[nt]);
                }
        }
        __syncthreads();
    }

    const int erow = lane >> 2;
    const int ecol = (lane & 3) * 2;

    if (mode == 1) {
        #pragma unroll
        for (int mt = 0; mt < 4; mt++)
            #pragma unroll
            for (int nt = 0; nt < 4; nt++) {
                int row = m0 + wm + mt * 16 + erow;
                int col = n0 + wn + nt * 8 + ecol;
                *(float2*)&Cp[(size_t)row * ldc + col] =
                    make_float2(c[mt][nt][0], c[mt][nt][1]);
                *(float2*)&Cp[(size_t)(row + 8) * ldc + col] =
                    make_float2(c[mt][nt][2], c[mt][nt][3]);
            }
    } else {
        const int which = n0 >> 10;
        bf16* dsth = (which == 0) ? g_qh : (which == 1) ? g_kh : g_vh;
        bf16* dstl = (which == 0) ? g_ql : (which == 1) ? g_kl : g_vl;
        const float sc = (which == 0) ? 0.125f : 1.0f;
        #pragma unroll
        for (int mt = 0; mt < 4; mt++)
            #pragma unroll
            for (int nt = 0; nt < 4; nt++) {
                int col = (n0 & 1023) + wn + nt * 8 + ecol;
                int h = col >> 6, dh = col & 63;
                #pragma unroll
                for (int rr = 0; rr < 2; rr++) {
                    int row = m0 + wm + mt * 16 + erow + rr * 8;
                    int b = row >> 11, l = row & 2047;
                    size_t base = ((size_t)((b << 4) + h) * 2048 + l) * 64 + dh;
                    float v0 = c[mt][nt][rr * 2 + 0] * sc;
                    float v1 = c[mt][nt][rr * 2 + 1] * sc;
                    bf16 h0, l0, h1, l1;
                    split_bf16(v0, h0, l0);
                    split_bf16(v1, h1, l1);
                    *(__nv_bfloat162*)(dsth + base) = __nv_bfloat162(h0, h1);
                    *(__nv_bfloat162*)(dstl + base) = __nv_bfloat162(l0, l1);
                }
            }
    }
}

// ---------------------------------------------------------------------------
// Flash attention, HMMA (unchanged from R5 — measured ~360 TF/s).
// ---------------------------------------------------------------------------
#define FP 72
#define FQ (128 * FP * 2)
#define FMAT (64 * FP * 2)
#define FSTAGE (4 * FMAT)
#define FLASH_SMEM (2 * FQ + 2 * FSTAGE)

__global__ __launch_bounds__(256) void flash_hmma()
{
    extern __shared__ char smem[];
    const uint32_t sb = smem_u32(smem);
    const uint32_t sQh = sb, sQl = sb + FQ;
    const uint32_t sKV = sb + 2 * FQ;

    const int tid  = threadIdx.x;
    const int wid  = tid >> 5;
    const int lane = tid & 31;
    const int bh   = blockIdx.y;
    const int q0   = blockIdx.x * 128;
    const int b    = bh >> 4;
    const int h    = bh & 15;

    const bf16* kvg[4] = {g_kh + (size_t)bh * 2048 * 64, g_kl + (size_t)bh * 2048 * 64,
                          g_vh + (size_t)bh * 2048 * 64, g_vl + (size_t)bh * 2048 * 64};

    {
        const bf16* qh_g = g_qh + (size_t)bh * 2048 * 64;
        const bf16* ql_g = g_ql + (size_t)bh * 2048 * 64;
        #pragma unroll
        for (int it = 0; it < 4; it++) {
            int i = tid + it * 256;
            int r = i >> 3, part = i & 7;
            uint4 v = *(const uint4*)(qh_g + (size_t)(q0 + r) * 64 + part * 8);
            *(uint4*)(smem + r * (FP * 2) + part * 16) = v;
            uint4 w = *(const uint4*)(ql_g + (size_t)(q0 + r) * 64 + part * 8);
            *(uint4*)(smem + FQ + r * (FP * 2) + part * 16) = w;
        }
    }

    #pragma unroll
    for (int it = 0; it < 8; it++) {
        int i = tid + it * 256;
        int mat = i >> 9, r = (i >> 3) & 63, part = i & 7;
        const bf16* src = kvg[mat] + (size_t)r * 64 + part * 8;
        uint32_t dst = sKV + mat * FMAT + r * (FP * 2) + part * 16;
        CP_ASYNC16(dst, src);
    }
    CP_COMMIT();
    __syncthreads();

    uint32_t qh[4][4], ql[4][4];
    #pragma unroll
    for (int ks = 0; ks < 4; ks++) {
        uint32_t off = (uint32_t)(wid * 16 + (lane & 15)) * (FP * 2)
                     + ks * 32 + (lane >> 4) * 16;
        ldsm_x4(qh[ks], sQh + off);
        ldsm_x4(ql[ks], sQl + off);
    }

    float o[8][4] = {};
    float mrow[2] = {-1e30f, -1e30f};
    float lrow[2] = {0.f, 0.f};

    for (int kb = 0; kb < 32; kb++) {
        CP_WAIT0();
        __syncthreads();

        if (kb + 1 < 32) {
            const uint32_t stg = sKV + ((kb + 1) & 1) * FSTAGE;
            const int krow0 = (kb + 1) * 64;
            #pragma unroll
            for (int it = 0; it < 8; it++) {
                int i = tid + it * 256;
                int mat = i >> 9, r = (i >> 3) & 63, part = i & 7;
                const bf16* src = kvg[mat] + (size_t)(krow0 + r) * 64 + part * 8;
                uint32_t dst = stg + mat * FMAT + r * (FP * 2) + part * 16;
                CP_ASYNC16(dst, src);
            }
            CP_COMMIT();
        }

        const uint32_t stg = sKV + (kb & 1) * FSTAGE;
        const uint32_t sKh = stg, sKl = stg + FMAT;
        const uint32_t sVh = stg + 2 * FMAT, sVl = stg + 3 * FMAT;

        float s[8][4] = {};
        #pragma unroll
        for (int ks = 0; ks < 4; ks++) {
            const uint32_t kc = (uint32_t)(ks * 32 + (lane >> 4) * 16);
            #pragma unroll
            for (int p = 0; p < 4; p++) {
                uint32_t kh4[4], kl4[4];
                uint32_t off = (uint32_t)(p * 16 + (lane & 15)) * (FP * 2) + kc;
                ldsm_x4(kh4, sKh + off);
                ldsm_x4(kl4, sKl + off);
                uint32_t b0h[2] = {kh4[0], kh4[2]}, b1h[2] = {kh4[1], kh4[3]};
                uint32_t b0l[2] = {kl4[0], kl4[2]}, b1l[2] = {kl4[1], kl4[3]};
                mma_bf16(s[2 * p],     qh[ks], b0h);
                mma_bf16(s[2 * p],     qh[ks], b0l);
                mma_bf16(s[2 * p],     ql[ks], b0h);
                mma_bf16(s[2 * p + 1], qh[ks], b1h);
                mma_bf16(s[2 * p + 1], qh[ks], b1l);
                mma_bf16(s[2 * p + 1], ql[ks], b1h);
            }
        }

        #pragma unroll
        for (int rh = 0; rh < 2; rh++) {
            float mx = -1e30f;
            #pragma unroll
            for (int nt = 0; nt < 8; nt++)
                mx = fmaxf(mx, fmaxf(s[nt][2 * rh], s[nt][2 * rh + 1]));
            mx = fmaxf(mx, __shfl_xor_sync(0xffffffffu, mx, 1));
            mx = fmaxf(mx, __shfl_xor_sync(0xffffffffu, mx, 2));
            float mnew = fmaxf(mrow[rh], mx);
            float corr = __expf(mrow[rh] - mnew);
            mrow[rh] = mnew;
            float rs = 0.f;
            #pragma unroll
            for (int nt = 0; nt < 8; nt++) {
                float p0 = __expf(s[nt][2 * rh] - mnew);
                float p1 = __expf(s[nt][2 * rh + 1] - mnew);
                s[nt][2 * rh] = p0;
                s[nt][2 * rh + 1] = p1;
                rs += p0 + p1;
            }
            rs += __shfl_xor_sync(0xffffffffu, rs, 1);
            rs += __shfl_xor_sync(0xffffffffu, rs, 2);
            lrow[rh] = lrow[rh] * corr + rs;
            #pragma unroll
            for (int nt = 0; nt < 8; nt++) {
                o[nt][2 * rh]     *= corr;
                o[nt][2 * rh + 1] *= corr;
            }
        }

        uint32_t ph[4][4], pl[4][4];
        #pragma unroll
        for (int ks = 0; ks < 4; ks++) {
            #pragma unroll
            for (int half = 0; half < 2; half++) {
                const float* sv = s[2 * ks + half];
                #pragma unroll
                for (int rr = 0; rr < 2; rr++) {
                    float v0 = sv[2 * rr], v1 = sv[2 * rr + 1];
                    bf16 h0, l0, h1, l1;
                    split_bf16(v0, h0, l0);
                    split_bf16(v1, h1, l1);
                    ph[ks][half * 2 + rr] = pack_bf16x2(__bfloat162float(h0),
                                                        __bfloat162float(h1));
                    pl[ks][half * 2 + rr] = pack_bf16x2(__bfloat162float(l0),
                                                        __bfloat162float(l1));
                }
            }
        }

        #pragma unroll
        for (int ks = 0; ks < 4; ks++) {
            #pragma unroll
            for (int p = 0; p < 4; p++) {
                uint32_t vh4[4], vl4[4];
                uint32_t off = (uint32_t)(ks * 16 + (lane & 15)) * (FP * 2)
                             + p * 32 + (lane >> 4) * 16;
                ldsm_x4_t(vh4, sVh + off);
                ldsm_x4_t(vl4, sVl + off);
                uint32_t b0h[2] = {vh4[0], vh4[1]}, b1h[2] = {vh4[2], vh4[3]};
                uint32_t b0l[2] = {vl4[0], vl4[1]}, b1l[2] = {vl4[2], vl4[3]};
                mma_bf16(o[2 * p],     ph[ks], b0h);
                mma_bf16(o[2 * p],     ph[ks], b0l);
                mma_bf16(o[2 * p],     pl[ks], b0h);
                mma_bf16(o[2 * p + 1], ph[ks], b1h);
                mma_bf16(o[2 * p + 1], ph[ks], b1l);
                mma_bf16(o[2 * p + 1], pl[ks], b1h);
            }
        }
    }

    const int erow = lane >> 2;
    const int ecol = (lane & 3) * 2;
    #pragma unroll
    for (int rh = 0; rh < 2; rh++) {
        float inv = 1.f / lrow[rh];
        int row = q0 + wid * 16 + erow + rh * 8;
        size_t rbase = (size_t)(b * 2048 + row) * 1024 + h * 64;
        #pragma unroll
        for (int nt = 0; nt < 8; nt++) {
            float v0 = o[nt][2 * rh] * inv;
            float v1 = o[nt][2 * rh + 1] * inv;
            bf16 h0, l0, h1, l1;
            split_bf16(v0, h0, l0);
            split_bf16(v1, h1, l1);
            size_t idx = rbase + nt * 8 + ecol;
            *(__nv_bfloat162*)(g_ctxh + idx) = __nv_bfloat162(h0, h1);
            *(__nv_bfloat162*)(g_ctxl + idx) = __nv_bfloat162(l0, l1);
        }
    }
}

// ---------------------------------------------------------------------------
extern "C" void kernel_launch(void* const* d_in, const int* in_sizes, int n_in,
                              void* d_out, int out_size)
{
    const float* x      = (const float*)d_in[0];
    const float* w_qkv  = (const float*)d_in[1];
    const float* w_proj = (const float*)d_in[2];
    float* out          = (float*)d_out;

    bf16 *xh, *xl, *wqh, *wql, *wph, *wpl, *ctxh, *ctxl;
    cudaGetSymbolAddress((void**)&xh, g_xh);
    cudaGetSymbolAddress((void**)&xl, g_xl);
    cudaGetSymbolAddress((void**)&wqh, g_wqh);
    cudaGetSymbolAddress((void**)&wql, g_wql);
    cudaGetSymbolAddress((void**)&wph, g_wph);
    cudaGetSymbolAddress((void**)&wpl, g_wpl);
    cudaGetSymbolAddress((void**)&ctxh, g_ctxh);
    cudaGetSymbolAddress((void**)&ctxl, g_ctxl);

    conv_split<<<(8192 * 1024 / 4 + 255) / 256, 256>>>(x, xh, xl, 8192 * 1024 / 4);
    conv_split<<<(3072 * 1024 / 4 + 255) / 256, 256>>>(w_qkv, wqh, wql, 3072 * 1024 / 4);
    conv_split<<<(1024 * 1024 / 4 + 255) / 256, 256>>>(w_proj, wph, wpl, 1024 * 1024 / 4);

    cudaFuncSetAttribute(flash_hmma,
                         cudaFuncAttributeMaxDynamicSharedMemorySize, FLASH_SMEM);

    // QKV: M=8192 N=3072
    hmma_gemm<<<dim3(24, 64), 256>>>(xh, xl, wqh, wql, nullptr, 0, 0);

    // flash: 16 q-tiles x 64 (b,h)
    flash_hmma<<<dim3(16, 64), 256, FLASH_SMEM>>>();

    // proj: M=8192 N=1024
    hmma_gemm<<<dim3(8, 64), 256>>>(ctxh, ctxl, wph, wpl, out, 1024, 1);
}

// round 7
// speedup vs baseline: 2.7463x; 1.0388x over previous
#include <cuda_runtime.h>
#include <cuda_bf16.h>
#include <math.h>
#include <stdint.h>

#define BB 4
#define LL 2048
#define DD 1024
#define HH 16
#define DHH 64

typedef __nv_bfloat16 bf16;

// ---------------- scratch (allocation-free device globals) ----------------
__device__ bf16 g_xh[(size_t)8192 * 1024], g_xl[(size_t)8192 * 1024];
__device__ bf16 g_wqh[(size_t)3072 * 1024], g_wql[(size_t)3072 * 1024];
__device__ bf16 g_wph[(size_t)1024 * 1024], g_wpl[(size_t)1024 * 1024];
__device__ bf16 g_qh[(size_t)64 * 2048 * 64], g_ql[(size_t)64 * 2048 * 64];
__device__ bf16 g_kh[(size_t)64 * 2048 * 64], g_kl[(size_t)64 * 2048 * 64];
__device__ bf16 g_vh[(size_t)64 * 2048 * 64], g_vl[(size_t)64 * 2048 * 64];
__device__ bf16 g_ctxh[(size_t)8192 * 1024], g_ctxl[(size_t)8192 * 1024];

// ---------------- PTX helpers ----------------
__device__ __forceinline__ uint32_t smem_u32(const void* p) {
    uint32_t a;
    asm("{ .reg .u64 t; cvta.to.shared.u64 t, %1; cvt.u32.u64 %0, t; }"
        : "=r"(a) : "l"(p));
    return a;
}
__device__ __forceinline__ void ldsm_x4(uint32_t* r, uint32_t addr) {
    asm volatile("ldmatrix.sync.aligned.m8n8.x4.shared.b16 {%0,%1,%2,%3}, [%4];"
                 : "=r"(r[0]), "=r"(r[1]), "=r"(r[2]), "=r"(r[3]) : "r"(addr));
}
__device__ __forceinline__ void ldsm_x4_t(uint32_t* r, uint32_t addr) {
    asm volatile("ldmatrix.sync.aligned.m8n8.x4.trans.shared.b16 {%0,%1,%2,%3}, [%4];"
                 : "=r"(r[0]), "=r"(r[1]), "=r"(r[2]), "=r"(r[3]) : "r"(addr));
}
__device__ __forceinline__ void mma_bf16(float* d, const uint32_t* a,
                                         const uint32_t* b) {
    asm volatile(
        "mma.sync.aligned.m16n8k16.row.col.f32.bf16.bf16.f32 "
        "{%0,%1,%2,%3}, {%4,%5,%6,%7}, {%8,%9}, {%0,%1,%2,%3};"
        : "+f"(d[0]), "+f"(d[1]), "+f"(d[2]), "+f"(d[3])
        : "r"(a[0]), "r"(a[1]), "r"(a[2]), "r"(a[3]), "r"(b[0]), "r"(b[1]));
}
#define CP_ASYNC16(dst, src) \
    asm volatile("cp.async.cg.shared.global [%0], [%1], 16;" \
                 :: "r"(dst), "l"(src) : "memory")
#define CP_COMMIT() asm volatile("cp.async.commit_group;" ::: "memory")
#define CP_WAIT0()  asm volatile("cp.async.wait_group 0;" ::: "memory")

__device__ __forceinline__ uint32_t pack_bf16x2(float a, float b) {
    __nv_bfloat162 t = __floats2bfloat162_rn(a, b);
    return *(uint32_t*)&t;
}
__device__ __forceinline__ void split_bf16(float v, bf16& h, bf16& l) {
    h = __float2bfloat16(v);
    l = __float2bfloat16(v - __bfloat162float(h));
}

// ---------------------------------------------------------------------------
// conv_split: fp32 -> (hi, lo) bf16, elementwise
// ---------------------------------------------------------------------------
__global__ void conv_split(const float* __restrict__ src, bf16* __restrict__ h,
                           bf16* __restrict__ l, int n4)
{
    int i = blockIdx.x * blockDim.x + threadIdx.x;
    if (i >= n4) return;
    float4 v = ((const float4*)src)[i];
    bf16 h0, l0, h1, l1, h2, l2, h3, l3;
    split_bf16(v.x, h0, l0); split_bf16(v.y, h1, l1);
    split_bf16(v.z, h2, l2); split_bf16(v.w, h3, l3);
    ((__nv_bfloat162*)h)[2 * i]     = __nv_bfloat162(h0, h1);
    ((__nv_bfloat162*)h)[2 * i + 1] = __nv_bfloat162(h2, h3);
    ((__nv_bfloat162*)l)[2 * i]     = __nv_bfloat162(l0, l1);
    ((__nv_bfloat162*)l)[2 * i + 1] = __nv_bfloat162(l2, l3);
}

// ---------------------------------------------------------------------------
// HMMA GEMM, tile 128x64x32 (occupancy-optimized): 8 warps 4x2, warp 32x32.
// Register prefetch -> static smem, ldmatrix + 3-term bf16-split MMA.
// mode 0: scatter bf16 hi/lo into g_q/g_k/g_v (q scaled). mode 1: fp32 -> Cp.
// ---------------------------------------------------------------------------
#define GP 40  // smem pitch in bf16 elems (80 B)

__global__ __launch_bounds__(256, 2) void hmma_gemm(
    const bf16* __restrict__ Ah_g, const bf16* __restrict__ Al_g,
    const bf16* __restrict__ Bh_g, const bf16* __restrict__ Bl_g,
    float* __restrict__ Cp, int ldc, int mode)
{
    __shared__ bf16 Ah[128][GP], Al[128][GP], Bh[64][GP], Bl[64][GP];

    const int tid  = threadIdx.x;
    const int wid  = tid >> 5;
    const int lane = tid & 31;
    const int m0   = blockIdx.y * 128;
    const int n0   = blockIdx.x * 64;
    const int wm   = (wid >> 1) * 32;   // 4 warps in m
    const int wn   = (wid & 1) * 32;    // 2 warps in n

    const uint32_t sAh = smem_u32(Ah), sAl = smem_u32(Al);
    const uint32_t sBh = smem_u32(Bh), sBl = smem_u32(Bl);

    // load mapping: A: idx=it*256+tid -> row=idx>>2 (128), part=idx&3
    //               B: idx=tid        -> row=tid>>2 (64),  part=tid&3
    const int arow = tid >> 2, apart = tid & 3;

    float c[2][4][4] = {};
    uint4 pA[2][2], pB[2];   // [hi/lo][it] / [hi/lo]

    {
        const bf16* Asrc[2] = {Ah_g, Al_g};
        const bf16* Bsrc[2] = {Bh_g, Bl_g};
        #pragma unroll
        for (int s = 0; s < 2; s++) {
            #pragma unroll
            for (int it = 0; it < 2; it++) {
                int row = arow + it * 64;
                pA[s][it] = *(const uint4*)(Asrc[s] + (size_t)(m0 + row) * 1024 + apart * 8);
            }
            pB[s] = *(const uint4*)(Bsrc[s] + (size_t)(n0 + arow) * 1024 + apart * 8);
        }
    }

    for (int ch = 0; ch < 32; ch++) {
        // store prefetched chunk to smem
        #pragma unroll
        for (int it = 0; it < 2; it++) {
            int row = arow + it * 64;
            *(uint4*)(&Ah[row][apart * 8]) = pA[0][it];
            *(uint4*)(&Al[row][apart * 8]) = pA[1][it];
        }
        *(uint4*)(&Bh[arow][apart * 8]) = pB[0];
        *(uint4*)(&Bl[arow][apart * 8]) = pB[1];
        __syncthreads();

        // prefetch next chunk (hidden under MMA block)
        if (ch + 1 < 32) {
            const int k0 = (ch + 1) * 32;
            const bf16* Asrc[2] = {Ah_g, Al_g};
            const bf16* Bsrc[2] = {Bh_g, Bl_g};
            #pragma unroll
            for (int s = 0; s < 2; s++) {
                #pragma unroll
                for (int it = 0; it < 2; it++) {
                    int row = arow + it * 64;
                    pA[s][it] = *(const uint4*)(Asrc[s] + (size_t)(m0 + row) * 1024
                                                + k0 + apart * 8);
                }
                pB[s] = *(const uint4*)(Bsrc[s] + (size_t)(n0 + arow) * 1024
                                        + k0 + apart * 8);
            }
        }

        #pragma unroll
        for (int ks = 0; ks < 2; ks++) {
            const uint32_t kc = (uint32_t)(ks * 32 + (lane >> 4) * 16);
            uint32_t ah[2][4], al[2][4];
            #pragma unroll
            for (int mt = 0; mt < 2; mt++) {
                uint32_t off = (uint32_t)(wm + mt * 16 + (lane & 15)) * (GP * 2) + kc;
                ldsm_x4(ah[mt], sAh + off);
                ldsm_x4(al[mt], sAl + off);
            }
            uint32_t bh[4][2], bl[4][2];
            #pragma unroll
            for (int half = 0; half < 2; half++) {
                uint32_t r4h[4], r4l[4];
                uint32_t off = (uint32_t)(wn + half * 16 + (lane & 15)) * (GP * 2) + kc;
                ldsm_x4(r4h, sBh + off);
                ldsm_x4(r4l, sBl + off);
                bh[half * 2 + 0][0] = r4h[0]; bh[half * 2 + 0][1] = r4h[2];
                bh[half * 2 + 1][0] = r4h[1]; bh[half * 2 + 1][1] = r4h[3];
                bl[half * 2 + 0][0] = r4l[0]; bl[half * 2 + 0][1] = r4l[2];
                bl[half * 2 + 1][0] = r4l[1]; bl[half * 2 + 1][1] = r4l[3];
            }
            #pragma unroll
            for (int mt = 0; mt < 2; mt++)
                #pragma unroll
                for (int nt = 0; nt < 4; nt++) {
                    mma_bf16(c[mt][nt], ah[mt], bh[nt]);
                    mma_bf16(c[mt][nt], ah[mt], bl[nt]);
                    mma_bf16(c[mt][nt], al[mt], bh[nt]);
                }
        }
        __syncthreads();
    }

    const int erow = lane >> 2;
    const int ecol = (lane & 3) * 2;

    if (mode == 1) {
        #pragma unroll
        for (int mt = 0; mt < 2; mt++)
            #pragma unroll
            for (int nt = 0; nt < 4; nt++) {
                int row = m0 + wm + mt * 16 + erow;
                int col = n0 + wn + nt * 8 + ecol;
                *(float2*)&Cp[(size_t)row * ldc + col] =
                    make_float2(c[mt][nt][0], c[mt][nt][1]);
                *(float2*)&Cp[(size_t)(row + 8) * ldc + col] =
                    make_float2(c[mt][nt][2], c[mt][nt][3]);
            }
    } else {
        const int which = n0 >> 10;
        bf16* dsth = (which == 0) ? g_qh : (which == 1) ? g_kh : g_vh;
        bf16* dstl = (which == 0) ? g_ql : (which == 1) ? g_kl : g_vl;
        const float sc = (which == 0) ? 0.125f : 1.0f;
        #pragma unroll
        for (int mt = 0; mt < 2; mt++)
            #pragma unroll
            for (int nt = 0; nt < 4; nt++) {
                int col = (n0 & 1023) + wn + nt * 8 + ecol;
                int h = col >> 6, dh = col & 63;
                #pragma unroll
                for (int rr = 0; rr < 2; rr++) {
                    int row = m0 + wm + mt * 16 + erow + rr * 8;
                    int b = row >> 11, l = row & 2047;
                    size_t base = ((size_t)((b << 4) + h) * 2048 + l) * 64 + dh;
                    float v0 = c[mt][nt][rr * 2 + 0] * sc;
                    float v1 = c[mt][nt][rr * 2 + 1] * sc;
                    bf16 h0, l0, h1, l1;
                    split_bf16(v0, h0, l0);
                    split_bf16(v1, h1, l1);
                    *(__nv_bfloat162*)(dsth + base) = __nv_bfloat162(h0, h1);
                    *(__nv_bfloat162*)(dstl + base) = __nv_bfloat162(l0, l1);
                }
            }
    }
}

// ---------------------------------------------------------------------------
// Flash attention, HMMA (unchanged).
// ---------------------------------------------------------------------------
#define FP 72
#define FQ (128 * FP * 2)
#define FMAT (64 * FP * 2)
#define FSTAGE (4 * FMAT)
#define FLASH_SMEM (2 * FQ + 2 * FSTAGE)

__global__ __launch_bounds__(256) void flash_hmma()
{
    extern __shared__ char smem[];
    const uint32_t sb = smem_u32(smem);
    const uint32_t sQh = sb, sQl = sb + FQ;
    const uint32_t sKV = sb + 2 * FQ;

    const int tid  = threadIdx.x;
    const int wid  = tid >> 5;
    const int lane = tid & 31;
    const int bh   = blockIdx.y;
    const int q0   = blockIdx.x * 128;
    const int b    = bh >> 4;
    const int h    = bh & 15;

    const bf16* kvg[4] = {g_kh + (size_t)bh * 2048 * 64, g_kl + (size_t)bh * 2048 * 64,
                          g_vh + (size_t)bh * 2048 * 64, g_vl + (size_t)bh * 2048 * 64};

    {
        const bf16* qh_g = g_qh + (size_t)bh * 2048 * 64;
        const bf16* ql_g = g_ql + (size_t)bh * 2048 * 64;
        #pragma unroll
        for (int it = 0; it < 4; it++) {
            int i = tid + it * 256;
            int r = i >> 3, part = i & 7;
            uint4 v = *(const uint4*)(qh_g + (size_t)(q0 + r) * 64 + part * 8);
            *(uint4*)(smem + r * (FP * 2) + part * 16) = v;
            uint4 w = *(const uint4*)(ql_g + (size_t)(q0 + r) * 64 + part * 8);
            *(uint4*)(smem + FQ + r * (FP * 2) + part * 16) = w;
        }
    }

    #pragma unroll
    for (int it = 0; it < 8; it++) {
        int i = tid + it * 256;
        int mat = i >> 9, r = (i >> 3) & 63, part = i & 7;
        const bf16* src = kvg[mat] + (size_t)r * 64 + part * 8;
        uint32_t dst = sKV + mat * FMAT + r * (FP * 2) + part * 16;
        CP_ASYNC16(dst, src);
    }
    CP_COMMIT();
    __syncthreads();

    uint32_t qh[4][4], ql[4][4];
    #pragma unroll
    for (int ks = 0; ks < 4; ks++) {
        uint32_t off = (uint32_t)(wid * 16 + (lane & 15)) * (FP * 2)
                     + ks * 32 + (lane >> 4) * 16;
        ldsm_x4(qh[ks], sQh + off);
        ldsm_x4(ql[ks], sQl + off);
    }

    float o[8][4] = {};
    float mrow[2] = {-1e30f, -1e30f};
    float lrow[2] = {0.f, 0.f};

    for (int kb = 0; kb < 32; kb++) {
        CP_WAIT0();
        __syncthreads();

        if (kb + 1 < 32) {
            const uint32_t stg = sKV + ((kb + 1) & 1) * FSTAGE;
            const int krow0 = (kb + 1) * 64;
            #pragma unroll
            for (int it = 0; it < 8; it++) {
                int i = tid + it * 256;
                int mat = i >> 9, r = (i >> 3) & 63, part = i & 7;
                const bf16* src = kvg[mat] + (size_t)(krow0 + r) * 64 + part * 8;
                uint32_t dst = stg + mat * FMAT + r * (FP * 2) + part * 16;
                CP_ASYNC16(dst, src);
            }
            CP_COMMIT();
        }

        const uint32_t stg = sKV + (kb & 1) * FSTAGE;
        const uint32_t sKh = stg, sKl = stg + FMAT;
        const uint32_t sVh = stg + 2 * FMAT, sVl = stg + 3 * FMAT;

        float s[8][4] = {};
        #pragma unroll
        for (int ks = 0; ks < 4; ks++) {
            const uint32_t kc = (uint32_t)(ks * 32 + (lane >> 4) * 16);
            #pragma unroll
            for (int p = 0; p < 4; p++) {
                uint32_t kh4[4], kl4[4];
                uint32_t off = (uint32_t)(p * 16 + (lane & 15)) * (FP * 2) + kc;
                ldsm_x4(kh4, sKh + off);
                ldsm_x4(kl4, sKl + off);
                uint32_t b0h[2] = {kh4[0], kh4[2]}, b1h[2] = {kh4[1], kh4[3]};
                uint32_t b0l[2] = {kl4[0], kl4[2]}, b1l[2] = {kl4[1], kl4[3]};
                mma_bf16(s[2 * p],     qh[ks], b0h);
                mma_bf16(s[2 * p],     qh[ks], b0l);
                mma_bf16(s[2 * p],     ql[ks], b0h);
                mma_bf16(s[2 * p + 1], qh[ks], b1h);
                mma_bf16(s[2 * p + 1], qh[ks], b1l);
                mma_bf16(s[2 * p + 1], ql[ks], b1h);
            }
        }

        #pragma unroll
        for (int rh = 0; rh < 2; rh++) {
            float mx = -1e30f;
            #pragma unroll
            for (int nt = 0; nt < 8; nt++)
                mx = fmaxf(mx, fmaxf(s[nt][2 * rh], s[nt][2 * rh + 1]));
            mx = fmaxf(mx, __shfl_xor_sync(0xffffffffu, mx, 1));
            mx = fmaxf(mx, __shfl_xor_sync(0xffffffffu, mx, 2));
            float mnew = fmaxf(mrow[rh], mx);
            float corr = __expf(mrow[rh] - mnew);
            mrow[rh] = mnew;
            float rs = 0.f;
            #pragma unroll
            for (int nt = 0; nt < 8; nt++) {
                float p0 = __expf(s[nt][2 * rh] - mnew);
                float p1 = __expf(s[nt][2 * rh + 1] - mnew);
                s[nt][2 * rh] = p0;
                s[nt][2 * rh + 1] = p1;
                rs += p0 + p1;
            }
            rs += __shfl_xor_sync(0xffffffffu, rs, 1);
            rs += __shfl_xor_sync(0xffffffffu, rs, 2);
            lrow[rh] = lrow[rh] * corr + rs;
            #pragma unroll
            for (int nt = 0; nt < 8; nt++) {
                o[nt][2 * rh]     *= corr;
                o[nt][2 * rh + 1] *= corr;
            }
        }

        uint32_t ph[4][4], pl[4][4];
        #pragma unroll
        for (int ks = 0; ks < 4; ks++) {
            #pragma unroll
            for (int half = 0; half < 2; half++) {
                const float* sv = s[2 * ks + half];
                #pragma unroll
                for (int rr = 0; rr < 2; rr++) {
                    float v0 = sv[2 * rr], v1 = sv[2 * rr + 1];
                    bf16 h0, l0, h1, l1;
                    split_bf16(v0, h0, l0);
                    split_bf16(v1, h1, l1);
                    ph[ks][half * 2 + rr] = pack_bf16x2(__bfloat162float(h0),
                                                        __bfloat162float(h1));
                    pl[ks][half * 2 + rr] = pack_bf16x2(__bfloat162float(l0),
                                                        __bfloat162float(l1));
                }
            }
        }

        #pragma unroll
        for (int ks = 0; ks < 4; ks++) {
            #pragma unroll
            for (int p = 0; p < 4; p++) {
                uint32_t vh4[4], vl4[4];
                uint32_t off = (uint32_t)(ks * 16 + (lane & 15)) * (FP * 2)
                             + p * 32 + (lane >> 4) * 16;
                ldsm_x4_t(vh4, sVh + off);
                ldsm_x4_t(vl4, sVl + off);
                uint32_t b0h[2] = {vh4[0], vh4[1]}, b1h[2] = {vh4[2], vh4[3]};
                uint32_t b0l[2] = {vl4[0], vl4[1]}, b1l[2] = {vl4[2], vl4[3]};
                mma_bf16(o[2 * p],     ph[ks], b0h);
                mma_bf16(o[2 * p],     ph[ks], b0l);
                mma_bf16(o[2 * p],     pl[ks], b0h);
                mma_bf16(o[2 * p + 1], ph[ks], b1h);
                mma_bf16(o[2 * p + 1], ph[ks], b1l);
                mma_bf16(o[2 * p + 1], pl[ks], b1h);
            }
        }
    }

    const int erow = lane >> 2;
    const int ecol = (lane & 3) * 2;
    #pragma unroll
    for (int rh = 0; rh < 2; rh++) {
        float inv = 1.f / lrow[rh];
        int row = q0 + wid * 16 + erow + rh * 8;
        size_t rbase = (size_t)(b * 2048 + row) * 1024 + h * 64;
        #pragma unroll
        for (int nt = 0; nt < 8; nt++) {
            float v0 = o[nt][2 * rh] * inv;
            float v1 = o[nt][2 * rh + 1] * inv;
            bf16 h0, l0, h1, l1;
            split_bf16(v0, h0, l0);
            split_bf16(v1, h1, l1);
            size_t idx = rbase + nt * 8 + ecol;
            *(__nv_bfloat162*)(g_ctxh + idx) = __nv_bfloat162(h0, h1);
            *(__nv_bfloat162*)(g_ctxl + idx) = __nv_bfloat162(l0, l1);
        }
    }
}

// ---------------------------------------------------------------------------
extern "C" void kernel_launch(void* const* d_in, const int* in_sizes, int n_in,
                              void* d_out, int out_size)
{
    const float* x      = (const float*)d_in[0];
    const float* w_qkv  = (const float*)d_in[1];
    const float* w_proj = (const float*)d_in[2];
    float* out          = (float*)d_out;

    bf16 *xh, *xl, *wqh, *wql, *wph, *wpl, *ctxh, *ctxl;
    cudaGetSymbolAddress((void**)&xh, g_xh);
    cudaGetSymbolAddress((void**)&xl, g_xl);
    cudaGetSymbolAddress((void**)&wqh, g_wqh);
    cudaGetSymbolAddress((void**)&wql, g_wql);
    cudaGetSymbolAddress((void**)&wph, g_wph);
    cudaGetSymbolAddress((void**)&wpl, g_wpl);
    cudaGetSymbolAddress((void**)&ctxh, g_ctxh);
    cudaGetSymbolAddress((void**)&ctxl, g_ctxl);

    conv_split<<<(8192 * 1024 / 4 + 255) / 256, 256>>>(x, xh, xl, 8192 * 1024 / 4);
    conv_split<<<(3072 * 1024 / 4 + 255) / 256, 256>>>(w_qkv, wqh, wql, 3072 * 1024 / 4);
    conv_split<<<(1024 * 1024 / 4 + 255) / 256, 256>>>(w_proj, wph, wpl, 1024 * 1024 / 4);

    cudaFuncSetAttribute(flash_hmma,
                         cudaFuncAttributeMaxDynamicSharedMemorySize, FLASH_SMEM);

    // QKV: M=8192, N=3072 -> grid (48, 64)
    hmma_gemm<<<dim3(48, 64), 256>>>(xh, xl, wqh, wql, nullptr, 0, 0);

    // flash: 16 q-tiles x 64 (b,h)
    flash_hmma<<<dim3(16, 64), 256, FLASH_SMEM>>>();

    // proj: M=8192, N=1024 -> grid (16, 64)
    hmma_gemm<<<dim3(16, 64), 256>>>(ctxh, ctxl, wph, wpl, out, 1024, 1);
}